// round 16
// baseline (speedup 1.0000x reference)
#include <cuda_runtime.h>
#include <cuda_bf16.h>
#include <math.h>

#define NP   512
#define NPIX (NP*NP)

__device__ __forceinline__ float2 cmul(float2 a, float2 b){
    return make_float2(a.x*b.x - a.y*b.y, a.x*b.y + a.y*b.x);
}
__device__ __forceinline__ float2 cadd(float2 a, float2 b){ return make_float2(a.x+b.x, a.y+b.y); }
__device__ __forceinline__ float2 csub(float2 a, float2 b){ return make_float2(a.x-b.x, a.y-b.y); }
__device__ __forceinline__ float2 cscale(float s, float2 a){ return make_float2(s*a.x, s*a.y); }
__device__ __forceinline__ float2 cdiv(float2 a, float2 b){
    float inv = 1.0f / (b.x*b.x + b.y*b.y);
    return make_float2((a.x*b.x + a.y*b.y)*inv, (a.y*b.x - a.x*b.y)*inv);
}

__device__ __forceinline__ void st(float* o, size_t i, float v, size_t nf){
    if (i < nf) o[i] = v;
}

__global__ __launch_bounds__(256)
void pupil_kernel(const float* __restrict__ ab,   // aberrations [12,3] float32
                  const float* __restrict__ zv,   // zvals [3] float32
                  float* __restrict__ outf, size_t nf)
{
    int idx = blockIdx.x * blockDim.x + threadIdx.x;
    if (idx >= NPIX) return;
    int i = idx >> 9;          // axis0 -> XP = xy[i]
    int j = idx & (NP - 1);    // axis1 -> YP = xy[j]

    const float dxy = 2.0f / (float)NP;
    float x = fmaf((float)i + 0.5f, dxy, -1.0f);
    float y = fmaf((float)j + 0.5f, dxy, -1.0f);
    float rhosq = __fadd_rn(__fmul_rn(x, x), __fmul_rn(y, y));

    const float nm = 1.33f, nc = 1.52f, ni = 1.52f;
    const float TWOPI_OVER_L = (float)(2.0 * M_PI / 640.0);
    const float KXY = (float)(2.0 * M_PI * 1.49 / 640.0);
    const float KZ  = (float)(2.0 * M_PI * 1.33 / 640.0);

    // CosThetaMed: sqrt(|a|)*(cos(phi/2) - i sin(phi/2)), phi = atan2(0,a) in {0,pi}
    float aMed = __fsub_rn(1.0f, __fdiv_rn(__fmul_rn(rhosq, 2.2201f), 1.7689f));
    float2 ctm = (aMed >= 0.0f) ? make_float2(sqrtf(aMed), 0.0f)
                                : make_float2(0.0f, -sqrtf(-aMed));
    // CosThetaCov/Imm/Immnom: principal complex sqrt (+i branch)
    float a2 = __fsub_rn(1.0f, __fdiv_rn(__fmul_rn(rhosq, 2.2201f), 2.3104f));
    float2 ct2 = (a2 >= 0.0f) ? make_float2(sqrtf(a2), 0.0f)
                              : make_float2(0.0f, sqrtf(-a2));

    // Fresnel med->cov (cov->imm factors == 1 since REFCOV==REFIMM)
    float2 fnum = cscale(2.0f * nm, ctm);
    float2 Fp = cdiv(fnum, cadd(cscale(nm, ct2), cscale(nc, ctm)));
    float2 Fs = cdiv(fnum, cadd(cscale(nm, ctm), cscale(nc, ct2)));

    // SinTheta = sqrt(1 - CosThetaMed^2) (real everywhere)
    float ST = sqrtf(1.0f - (ctm.x*ctm.x - ctm.y*ctm.y));

    float rinv = rsqrtf(rhosq);
    float c1 = x * rinv, s1 = y * rinv;
    float c2 = c1*c1 - s1*s1;
    float s2 = 2.0f * c1 * s1;
    float c3 = c1*c2 - s1*s2;
    float s3 = s1*c2 + c1*s2;

    float rho = sqrtf(rhosq);
    float r2 = rhosq, r3 = rho*r2, r4 = r2*r2, r5 = r4*rho, r6 = r4*r2;
    const float SQ5  = 2.23606797749979f;
    const float SQ6  = 2.449489742783178f;
    const float SQ7  = 2.6457513110645907f;
    const float SQ8  = 2.8284271247461903f;
    const float SQ10 = 3.1622776601683795f;
    const float SQ12 = 3.4641016151377544f;

    float cf0=ab[2],  cf1=ab[5],  cf2=ab[8],   cf3=ab[11];
    float cf4=ab[14], cf5=ab[17], cf6=ab[20],  cf7=ab[23];
    float cf8=ab[26], cf9=ab[29], cf10=ab[32], cf11=ab[35];
    float z0=zv[0], z1=zv[1], z2=zv[2];

    float R31 = 3.0f*r3 - 2.0f*rho;
    float R40 = 6.0f*r4 - 6.0f*r2 + 1.0f;
    float R42 = 4.0f*r4 - 3.0f*r2;
    float R51 = 10.0f*r5 - 12.0f*r3 + 3.0f*rho;
    float R60 = 20.0f*r6 - 30.0f*r4 + 12.0f*r2 - 1.0f;

    float W_ab =
          (SQ6 *cf0 )*(r2 *s2) + (SQ6 *cf1 )*(r2 *c2)
        + (SQ8 *cf2 )*(R31*s1) + (SQ8 *cf3 )*(R31*c1)
        + (SQ5 *cf4 )* R40
        + (SQ8 *cf5 )*(r3 *s3) + (SQ8 *cf6 )*(r3 *c3)
        + (SQ10*cf7 )*(R42*s2) + (SQ10*cf8 )*(R42*c2)
        + (SQ12*cf9 )*(R51*s1) + (SQ12*cf10)*(R51*c1)
        + (SQ7 *cf11)* R60;

    // Re(W) = W_ab + (z0 - z1)*ni*Re(CT2) - z2*nm*Re(CTM)
    float Wre = W_ab + z0*ni*ct2.x - z1*ni*ct2.x - z2*nm*ctm.x;

    // PhaseFactor = exp(+i * 2pi * Re(W)/lambda)
    float theta = TWOPI_OVER_L * Wre;
    float sp, cp;
    sincosf(theta, &sp, &cp);
    float2 phase = make_float2(cp, sp);

    // Amplitude = sqrt(CT2)/(nm*CTM) inside mask
    float san = sqrtf(fmaxf(ct2.x, 0.0f));
    float2 den = cscale(nm, ctm);
    float dinv = 1.0f / (den.x*den.x + den.y*den.y);
    float2 Amp = make_float2(san*den.x*dinv, -san*den.y*dinv);

    float mask = (rhosq < 1.0f) ? 1.0f : 0.0f;
    float2 E = cscale(mask, cmul(Amp, phase));

    float2 A = cmul(Fp, ctm);
    float cc = c1*c1, ss = s1*s1, cs = c1*s1;
    float2 M00 = make_float2(A.x*cc + Fs.x*ss, A.y*cc + Fs.y*ss);
    float2 M01 = cscale(cs, csub(A, Fs));
    float2 M02 = cscale(-ST*c1, Fp);
    float2 M11 = make_float2(A.x*ss + Fs.x*cc, A.y*ss + Fs.y*cc);
    float2 M12 = cscale(-ST*s1, Fp);

    float2 e00 = cmul(E, M00);
    float2 e01 = cmul(E, M01);   // == e10
    float2 e02 = cmul(E, M02);
    float2 e11 = cmul(E, M11);
    float2 e12 = cmul(E, M12);

    // ---- REAL-PART-ONLY float32 serialization (out buffer = 10N floats) ----
    // Output 0: Re(PM) [512,512,2,3] C-order at [0, 6N)
    {
        size_t e = (size_t)idx * 6;
        st(outf, e+0, e00.x, nf);
        st(outf, e+1, e01.x, nf);
        st(outf, e+2, e02.x, nf);
        st(outf, e+3, e01.x, nf);   // PM[1][0] == PM[0][1]
        st(outf, e+4, e11.x, nf);
        st(outf, e+5, e12.x, nf);
    }
    // Output 1: Re(W)*mask at [6N, 7N)
    st(outf, (size_t)NPIX*6 + idx, Wre * mask, nf);

    // Output 2: Re(wavevector) [512,512,3] at [7N, 10N)
    {
        size_t e = (size_t)NPIX*7 + (size_t)idx*3;
        st(outf, e+0, KXY * x,    nf);
        st(outf, e+1, KXY * y,    nf);
        st(outf, e+2, KZ * ctm.x, nf);
    }
}

extern "C" void kernel_launch(void* const* d_in, const int* in_sizes, int n_in,
                              void* d_out, int out_size) {
    const float* ab = (const float*)d_in[0];
    const float* zv = (const float*)(n_in >= 2 ? d_in[1] : d_in[0]);
    if (n_in >= 2 && in_sizes[1] > in_sizes[0]) {
        ab = (const float*)d_in[1];
        zv = (const float*)d_in[0];
    }

    // Established: output dtype float32, real parts only, total = 10N floats.
    const size_t FULL_F = (size_t)NPIX * 10;   // 2,621,440 floats
    size_t nf = (size_t)(out_size > 0 ? out_size : 0);
    if (nf > FULL_F) nf = FULL_F;

    pupil_kernel<<<NPIX/256, 256>>>(ab, zv, (float*)d_out, nf);
}

// round 17
// speedup vs baseline: 1.4981x; 1.4981x over previous
#include <cuda_runtime.h>
#include <math.h>

#define NP   512
#define NPIX (NP*NP)

__global__ __launch_bounds__(256)
void pupil_kernel(const float* __restrict__ ab,   // aberrations [12,3] float32
                  const float* __restrict__ zv,   // zvals [3] float32
                  float* __restrict__ outf)       // 10N floats: [RePM|ReW|ReWv]
{
    int idx = blockIdx.x * blockDim.x + threadIdx.x;   // grid exactly covers NPIX
    int i = idx >> 9;          // axis0 -> XP = xy[i]
    int j = idx & (NP - 1);    // axis1 -> YP = xy[j]

    const float dxy = 2.0f / (float)NP;
    float x = fmaf((float)i + 0.5f, dxy, -1.0f);
    float y = fmaf((float)j + 0.5f, dxy, -1.0f);
    float rhosq = x*x + y*y;

    const float K1   = (float)(2.2201 / 1.7689);    // NA^2/REFMED^2
    const float K2   = (float)(2.2201 / 2.3104);    // NA^2/REFCOV^2
    const float SQK1 = 1.1203007f;                  // sqrt(K1)
    const float nm = 1.33f, nc = 1.52f, ni = 1.52f;
    const float TWOPI_OVER_L = (float)(2.0 * M_PI / 640.0);
    const float KXY = (float)(2.0 * M_PI * 1.49 / 640.0);
    const float KZ  = (float)(2.0 * M_PI * 1.33 / 640.0);

    // CosThetaMed: -i branch below critical ring; CosThetaCov: +i branch
    float aMed = 1.0f - rhosq * K1;
    float sa = sqrtf(fabsf(aMed));                         // MUFU 1
    float2 ctm = (aMed >= 0.0f) ? make_float2(sa, 0.0f) : make_float2(0.0f, -sa);
    float a2 = 1.0f - rhosq * K2;
    float sb = sqrtf(fabsf(a2));                           // MUFU 2
    float2 ct2 = (a2 >= 0.0f) ? make_float2(sb, 0.0f) : make_float2(0.0f, sb);

    // Fresnel denominators (cov->imm factors == 1 since REFCOV==REFIMM)
    float2 d1 = make_float2(nm*ct2.x + nc*ctm.x, nm*ct2.y + nc*ctm.y);
    float2 d2 = make_float2(nm*ctm.x + nc*ct2.x, nm*ctm.y + nc*ct2.y);

    // Batched reciprocals: 1/q1, 1/q2, 1/q3 from ONE division
    float q1 = d1.x*d1.x + d1.y*d1.y;
    float q2 = d2.x*d2.x + d2.y*d2.y;
    float q3 = (nm*nm) * (ctm.x*ctm.x + ctm.y*ctm.y);      // |nm*ctm|^2 (validated nonzero)
    float invall = __fdividef(1.0f, q1 * q2 * q3);         // MUFU 3
    float i1 = invall * (q2 * q3);
    float i2 = invall * (q1 * q3);
    float i3 = invall * (q1 * q2);

    // fnum = 2*nm*ctm;  Fp = fnum/d1, Fs = fnum/d2 (complex)
    float2 fnum = make_float2(2.0f*nm*ctm.x, 2.0f*nm*ctm.y);
    float2 Fp = make_float2((fnum.x*d1.x + fnum.y*d1.y)*i1, (fnum.y*d1.x - fnum.x*d1.y)*i1);
    float2 Fs = make_float2((fnum.x*d2.x + fnum.y*d2.y)*i2, (fnum.y*d2.x - fnum.x*d2.y)*i2);

    // cos/sin phi; rho and SinTheta without extra sqrt:
    // ctm^2 == aMed in BOTH branches  =>  SinTheta = sqrt(1-aMed) = rho*sqrt(K1)
    float rinv = rsqrtf(rhosq);                            // MUFU 4
    float rho  = rhosq * rinv;
    float ST   = rho * SQK1;
    float c1 = x * rinv, s1 = y * rinv;
    float c2 = c1*c1 - s1*s1;
    float s2 = 2.0f * c1 * s1;
    float c3 = c1*c2 - s1*s2;
    float s3 = s1*c2 + c1*s2;

    float r2 = rhosq, r3 = rho*r2, r4 = r2*r2, r5 = r4*rho, r6 = r4*r2;
    const float SQ5  = 2.23606797749979f;
    const float SQ6  = 2.449489742783178f;
    const float SQ7  = 2.6457513110645907f;
    const float SQ8  = 2.8284271247461903f;
    const float SQ10 = 3.1622776601683795f;
    const float SQ12 = 3.4641016151377544f;

    float cf0=ab[2],  cf1=ab[5],  cf2=ab[8],   cf3=ab[11];
    float cf4=ab[14], cf5=ab[17], cf6=ab[20],  cf7=ab[23];
    float cf8=ab[26], cf9=ab[29], cf10=ab[32], cf11=ab[35];
    float za = (zv[0] - zv[1]) * ni;
    float zb = zv[2] * nm;

    float R31 = 3.0f*r3 - 2.0f*rho;
    float R40 = 6.0f*r4 - 6.0f*r2 + 1.0f;
    float R42 = 4.0f*r4 - 3.0f*r2;
    float R51 = 10.0f*r5 - 12.0f*r3 + 3.0f*rho;
    float R60 = 20.0f*r6 - 30.0f*r4 + 12.0f*r2 - 1.0f;

    float W_ab =
          (SQ6 *cf0 )*(r2 *s2) + (SQ6 *cf1 )*(r2 *c2)
        + (SQ8 *cf2 )*(R31*s1) + (SQ8 *cf3 )*(R31*c1)
        + (SQ5 *cf4 )* R40
        + (SQ8 *cf5 )*(r3 *s3) + (SQ8 *cf6 )*(r3 *c3)
        + (SQ10*cf7 )*(R42*s2) + (SQ10*cf8 )*(R42*c2)
        + (SQ12*cf9 )*(R51*s1) + (SQ12*cf10)*(R51*c1)
        + (SQ7 *cf11)* R60;

    // Re(W) = W_ab + (z0-z1)*ni*Re(CT2) - z2*nm*Re(CTM)
    float Wre = W_ab + za*ct2.x - zb*ctm.x;

    // PhaseFactor = exp(+i*2pi*Re(W)/lambda)
    float theta = TWOPI_OVER_L * Wre;
    float sp, cp;
    __sincosf(theta, &sp, &cp);                            // MUFU 5,6

    // Amplitude = sqrt(Re(CT2))/(nm*CTM) inside mask  (complex reciprocal via i3)
    float san = sqrtf(fmaxf(ct2.x, 0.0f));                 // MUFU 7
    float2 Amp = make_float2(san * (nm*ctm.x) * i3, -san * (nm*ctm.y) * i3);

    float mask = (rhosq < 1.0f) ? 1.0f : 0.0f;
    // E = mask * Amp * phase
    float2 E = make_float2(mask * (Amp.x*cp - Amp.y*sp), mask * (Amp.x*sp + Amp.y*cp));

    // A = Fp * CosThetaMed (complex)
    float2 A = make_float2(Fp.x*ctm.x - Fp.y*ctm.y, Fp.x*ctm.y + Fp.y*ctm.x);
    float cc = c1*c1, ss = s1*s1, cs = c1*s1;

    float2 M00 = make_float2(A.x*cc + Fs.x*ss, A.y*cc + Fs.y*ss);
    float2 M01 = make_float2(cs*(A.x - Fs.x), cs*(A.y - Fs.y));
    float2 M02 = make_float2(-ST*c1*Fp.x, -ST*c1*Fp.y);
    float2 M11 = make_float2(A.x*ss + Fs.x*cc, A.y*ss + Fs.y*cc);
    float2 M12 = make_float2(-ST*s1*Fp.x, -ST*s1*Fp.y);

    // Only real parts of E*M are stored (imag dead-code eliminated)
    float e0 = E.x*M00.x - E.y*M00.y;
    float e1 = E.x*M01.x - E.y*M01.y;
    float e2 = E.x*M02.x - E.y*M02.y;
    float e4 = E.x*M11.x - E.y*M11.y;
    float e5 = E.x*M12.x - E.y*M12.y;

    // ---- stores (layout proven in R16): Re(PM) | Re(W) | Re(wv) ----
    float2* pm2 = reinterpret_cast<float2*>(outf) + (size_t)idx * 3;  // 8B-aligned
    pm2[0] = make_float2(e0, e1);
    pm2[1] = make_float2(e2, e1);    // PM[0][2], PM[1][0]==PM[0][1]
    pm2[2] = make_float2(e4, e5);

    outf[(size_t)NPIX*6 + idx] = Wre * mask;

    size_t v = (size_t)NPIX*7 + (size_t)idx*3;
    outf[v+0] = KXY * x;
    outf[v+1] = KXY * y;
    outf[v+2] = KZ * ctm.x;
}

extern "C" void kernel_launch(void* const* d_in, const int* in_sizes, int n_in,
                              void* d_out, int out_size) {
    const float* ab = (const float*)d_in[0];
    const float* zv = (const float*)(n_in >= 2 ? d_in[1] : d_in[0]);
    if (n_in >= 2 && in_sizes[1] > in_sizes[0]) {
        ab = (const float*)d_in[1];
        zv = (const float*)d_in[0];
    }
    pupil_kernel<<<NPIX/256, 256>>>(ab, zv, (float*)d_out);
}